// round 13
// baseline (speedup 1.0000x reference)
#include <cuda_runtime.h>
#include <cstdint>

// DistEmb forward: out[i, :] = table[idx[i], :]
// table: [2e6, 128] fp32 (1 GB), idx: [1,048,576] int32, out: 512 MB fp32.
//
// R9: L2 eviction-priority split, fixed for sm_103 ptxas rules:
// .L2::evict_last is only legal on 256-bit loads (.v4.b64), so table gathers
// use 32B-per-lane loads. Row = 512B = 16 lanes x 32B -> each warp gathers
// TWO rows per batch (half-warp-uniform idx). Stores stay evict-first (.cs)
// 16B bursts so the 512MB write stream never displaces pinned table lines.
// L2 (~126MB) then holds ~31% of the 403MB distinct-row set -> more of the
// ~26% duplicate reads hit in L2.

static constexpr int THREADS         = 256;  // 8 warps / block
static constexpr int ROW_PAIRS       = 4;    // batches per warp pass
static constexpr int ROWS_PER_WARP   = 2 * ROW_PAIRS;  // 8
static constexpr int ROW_BYTES       = 512;  // 128 fp32

// 32B table load, non-coherent, L2 evict-last priority (256-bit form).
__device__ __forceinline__ ulonglong4 ldg32_evict_last(const void* p)
{
    ulonglong4 v;
    asm volatile("ld.global.nc.L2::evict_last.v4.b64 {%0,%1,%2,%3}, [%4];"
                 : "=l"(v.x), "=l"(v.y), "=l"(v.z), "=l"(v.w)
                 : "l"(p));
    return v;
}

// 32B store as two 16B evict-first (.cs) stores.
__device__ __forceinline__ void st32_cs(void* p, ulonglong4 v)
{
    asm volatile("st.global.cs.v2.b64 [%0], {%1,%2};"
                 :: "l"(p), "l"(v.x), "l"(v.y) : "memory");
    asm volatile("st.global.cs.v2.b64 [%0], {%1,%2};"
                 :: "l"((char*)p + 16), "l"(v.z), "l"(v.w) : "memory");
}

__global__ __launch_bounds__(THREADS)
void distemb_gather_kernel(const char* __restrict__ table,
                           const int* __restrict__ idx,
                           char* __restrict__ out,
                           int num_ids)
{
    const int gwarp  = (blockIdx.x * THREADS + threadIdx.x) >> 5;
    const int lane   = threadIdx.x & 31;
    const int rsub   = lane >> 4;        // 0 or 1: which row of the pair
    const int chunk  = lane & 15;        // 32B chunk within the row
    const int row0   = gwarp * ROWS_PER_WARP;
    if (row0 >= num_ids) return;

    const size_t coff = (size_t)chunk * 32;

    if (row0 + ROWS_PER_WARP <= num_ids) {
        // Fast path: 8 rows = 4 pairs; loads fully batched before stores.
        int src[ROW_PAIRS];
        int row[ROW_PAIRS];
#pragma unroll
        for (int b = 0; b < ROW_PAIRS; b++) {
            row[b] = row0 + 2 * b + rsub;
            src[b] = __ldg(&idx[row[b]]);          // half-warp-uniform
        }

        ulonglong4 v[ROW_PAIRS];
#pragma unroll
        for (int b = 0; b < ROW_PAIRS; b++)        // 4 independent 32B LDGs
            v[b] = ldg32_evict_last(table + (size_t)src[b] * ROW_BYTES + coff);

#pragma unroll
        for (int b = 0; b < ROW_PAIRS; b++)        // evict-first store bursts
            st32_cs(out + (size_t)row[b] * ROW_BYTES + coff, v[b]);
    } else {
        // Tail: plain 16B-per-lane path (never taken for 1M ids, 64 rows/warp).
        for (int r = 0; row0 + r < num_ids; r++) {
            const int src = __ldg(&idx[row0 + r]);
            const float4* tp = (const float4*)(table + (size_t)src * ROW_BYTES) + lane;
            float4* op = (float4*)(out + (size_t)(row0 + r) * ROW_BYTES) + lane;
            __stcs(op, __ldg(tp));
        }
    }
}

extern "C" void kernel_launch(void* const* d_in, const int* in_sizes, int n_in,
                              void* d_out, int out_size)
{
    // Identify inputs by element count (table: 268,435,456 elems; idx: 1,048,576).
    const void* table_p = d_in[0];
    const void* idx_p   = d_in[1];
    int         idx_n   = in_sizes[1];
    if (n_in >= 2 && in_sizes[0] < in_sizes[1]) {
        table_p = d_in[1];
        idx_p   = d_in[0];
        idx_n   = in_sizes[0];
    }

    const char* table = (const char*)table_p;
    const int*  idx   = (const int*)idx_p;
    char*       out   = (char*)d_out;

    const int rows_per_block = (THREADS / 32) * ROWS_PER_WARP;  // 64
    const int grid = (idx_n + rows_per_block - 1) / rows_per_block;

    distemb_gather_kernel<<<grid, THREADS>>>(table, idx, out, idx_n);
}

// round 16
// speedup vs baseline: 1.0238x; 1.0238x over previous
#include <cuda_runtime.h>
#include <cstdint>

// DistEmb forward: out[i, :] = table[idx[i], :]
// table: [2e6, 128] fp32 (1 GB), idx: [1,048,576] int32, out: 512 MB fp32.
//
// FINAL (R4 config, best measured: 158.5us total, 82% of HBM spec).
// One warp per 4 rows: 4 warp-uniform idx loads, 4 independent 16B/lane
// gathers (fully coalesced 512B bursts, MLP=4), then 4 streaming __stcs
// stores (evict-first) so the 512MB write stream doesn't displace gathered
// table rows from L2.
//
// Levers tested and rejected with evidence:
//  - bucket-sorted processing order: scatter atomics cost 56us, sorted
//    gather saved only ~5us (write stream randomized)        -> REGRESSED
//  - MLP 4->8: neutral (DRAM queues already full at occ ~84%) -> NEUTRAL
//  - __stwt write-through stores: neutral                     -> NEUTRAL
//  - 32B ld.global.nc.L2::evict_last + split .cs stores: more L1/LTS work,
//    no read-traffic reduction (reuse distance >> L2)         -> REGRESSED
// Conclusion: ~6.55 TB/s is the practical HBM ceiling for random 512B
// gather + streamed writeback on this part.

static constexpr int EMB_F4        = 32;  // 128 floats = 32 float4
static constexpr int THREADS       = 256; // 8 warps / block
static constexpr int ROWS_PER_WARP = 4;

__global__ __launch_bounds__(THREADS)
void distemb_gather_kernel(const float4* __restrict__ table,
                           const int* __restrict__ idx,
                           float4* __restrict__ out,
                           int num_ids)
{
    const int gwarp = (blockIdx.x * THREADS + threadIdx.x) >> 5;
    const int lane  = threadIdx.x & 31;
    const int row0  = gwarp * ROWS_PER_WARP;
    if (row0 >= num_ids) return;

    if (row0 + ROWS_PER_WARP <= num_ids) {
        // Fast path: 4 rows, loads fully batched before stores.
        int src[ROWS_PER_WARP];
#pragma unroll
        for (int r = 0; r < ROWS_PER_WARP; r++)
            src[r] = __ldg(&idx[row0 + r]);        // warp-uniform broadcasts

        float4 v[ROWS_PER_WARP];
#pragma unroll
        for (int r = 0; r < ROWS_PER_WARP; r++)    // 4 independent LDG.128
            v[r] = __ldg(&table[(size_t)src[r] * EMB_F4 + lane]);

#pragma unroll
        for (int r = 0; r < ROWS_PER_WARP; r++)    // streaming, evict-first
            __stcs(&out[(size_t)(row0 + r) * EMB_F4 + lane], v[r]);
    } else {
        for (int r = 0; row0 + r < num_ids; r++) {
            const int src = __ldg(&idx[row0 + r]);
            float4 v = __ldg(&table[(size_t)src * EMB_F4 + lane]);
            __stcs(&out[(size_t)(row0 + r) * EMB_F4 + lane], v);
        }
    }
}

extern "C" void kernel_launch(void* const* d_in, const int* in_sizes, int n_in,
                              void* d_out, int out_size)
{
    // Identify inputs by element count (table: 268,435,456 elems; idx: 1,048,576).
    const void* table_p = d_in[0];
    const void* idx_p   = d_in[1];
    int         idx_n   = in_sizes[1];
    if (n_in >= 2 && in_sizes[0] < in_sizes[1]) {
        table_p = d_in[1];
        idx_p   = d_in[0];
        idx_n   = in_sizes[0];
    }

    const float4* table = (const float4*)table_p;
    const int*    idx   = (const int*)idx_p;
    float4*       out   = (float4*)d_out;

    const int rows_per_block = (THREADS / 32) * ROWS_PER_WARP;  // 32
    const int grid = (idx_n + rows_per_block - 1) / rows_per_block;

    distemb_gather_kernel<<<grid, THREADS>>>(table, idx, out, idx_n);
}

// round 17
// speedup vs baseline: 1.0276x; 1.0036x over previous
#include <cuda_runtime.h>
#include <cstdint>

// DistEmb forward: out[i, :] = table[idx[i], :]
// table: [2e6, 128] fp32 (1 GB), idx: [1,048,576] int32, out: 512 MB fp32.
//
// R17: R4-final with one micro-change — table gathers use __ldcg (L2-only,
// no L1 allocation). Random 512B rows have ~0 L1 hit probability (228KB L1
// vs 403MB distinct working set); skipping L1 allocation trims L1tex
// wavefront/replay work. Everything else identical to the measured-best
// config (158.5us, DRAM 82.6%, ~LTS chip cap).
//
// Evidence ledger (what's been tried):
//  - bucket-sort order:    REGRESSED (+61us; scatter atomics 56us)
//  - MLP 4->8:             NEUTRAL   (queues already full, occ ~84%)
//  - __stwt stores:        NEUTRAL   (write-alloc wasn't displacing reuse)
//  - 32B evict_last loads: REGRESSED (+5.8us; more LTS/L1 work, no dedup)
// Binding constraint: ~1.0GB through LTS at ~6.55TB/s ≈ chip LTS cap.

static constexpr int EMB_F4        = 32;  // 128 floats = 32 float4
static constexpr int THREADS       = 256; // 8 warps / block
static constexpr int ROWS_PER_WARP = 4;

__global__ __launch_bounds__(THREADS)
void distemb_gather_kernel(const float4* __restrict__ table,
                           const int* __restrict__ idx,
                           float4* __restrict__ out,
                           int num_ids)
{
    const int gwarp = (blockIdx.x * THREADS + threadIdx.x) >> 5;
    const int lane  = threadIdx.x & 31;
    const int row0  = gwarp * ROWS_PER_WARP;
    if (row0 >= num_ids) return;

    if (row0 + ROWS_PER_WARP <= num_ids) {
        // Fast path: 4 rows, loads fully batched before stores.
        int src[ROWS_PER_WARP];
#pragma unroll
        for (int r = 0; r < ROWS_PER_WARP; r++)
            src[r] = __ldg(&idx[row0 + r]);        // warp-uniform broadcasts

        float4 v[ROWS_PER_WARP];
#pragma unroll
        for (int r = 0; r < ROWS_PER_WARP; r++)    // 4 independent LDG.128.CG
            v[r] = __ldcg(&table[(size_t)src[r] * EMB_F4 + lane]);

#pragma unroll
        for (int r = 0; r < ROWS_PER_WARP; r++)    // streaming, evict-first
            __stcs(&out[(size_t)(row0 + r) * EMB_F4 + lane], v[r]);
    } else {
        for (int r = 0; row0 + r < num_ids; r++) {
            const int src = __ldg(&idx[row0 + r]);
            float4 v = __ldcg(&table[(size_t)src * EMB_F4 + lane]);
            __stcs(&out[(size_t)(row0 + r) * EMB_F4 + lane], v);
        }
    }
}

extern "C" void kernel_launch(void* const* d_in, const int* in_sizes, int n_in,
                              void* d_out, int out_size)
{
    // Identify inputs by element count (table: 268,435,456 elems; idx: 1,048,576).
    const void* table_p = d_in[0];
    const void* idx_p   = d_in[1];
    int         idx_n   = in_sizes[1];
    if (n_in >= 2 && in_sizes[0] < in_sizes[1]) {
        table_p = d_in[1];
        idx_p   = d_in[0];
        idx_n   = in_sizes[0];
    }

    const float4* table = (const float4*)table_p;
    const int*    idx   = (const int*)idx_p;
    float4*       out   = (float4*)d_out;

    const int rows_per_block = (THREADS / 32) * ROWS_PER_WARP;  // 32
    const int grid = (idx_n + rows_per_block - 1) / rows_per_block;

    distemb_gather_kernel<<<grid, THREADS>>>(table, idx, out, idx_n);
}